// round 1
// baseline (speedup 1.0000x reference)
#include <cuda_runtime.h>
#include <math.h>

#define F 128
#define MAXN 50000

// Scratch (allocation-free rule: __device__ globals)
__device__ float g_bufA[MAXN * F];
__device__ float g_bufB[MAXN * F];
__device__ float g_bufC[MAXN * F];

// ---------------------------------------------------------------------------
__global__ void zero_kernel(float* __restrict__ p, int n4) {
    int i = blockIdx.x * blockDim.x + threadIdx.x;
    float4 z = make_float4(0.f, 0.f, 0.f, 0.f);
    for (; i < n4; i += gridDim.x * blockDim.x) ((float4*)p)[i] = z;
}

// out[widx[e]] += x[ridx[e]]   (row width F=128 floats)
// One warp per edge; each lane handles one float4 chunk; vector RED (v4.f32).
__global__ void scatter_add_kernel(const float* __restrict__ x,
                                   const int* __restrict__ widx,
                                   const int* __restrict__ ridx,
                                   float* __restrict__ out, int nedges) {
    int tid   = blockIdx.x * blockDim.x + threadIdx.x;
    int lane  = threadIdx.x & 31;
    int nwarp = (gridDim.x * blockDim.x) >> 5;
    for (int e = tid >> 5; e < nedges; e += nwarp) {
        int w = __ldg(widx + e);
        int r = __ldg(ridx + e);
        float4 v = ((const float4*)(x + (size_t)r * F))[lane];
        float* dst = out + (size_t)w * F + lane * 4;
        asm volatile("red.global.add.v4.f32 [%0], {%1,%2,%3,%4};"
                     :: "l"(dst), "f"(v.x), "f"(v.y), "f"(v.z), "f"(v.w)
                     : "memory");
    }
}

// C[M x NOUT] = act( (scale*A + (HASB2 ? B2 : 0)) @ W[128 x nout_actual] + bias )
// W cached in smem (padded to NOUT cols). Thread computes a 1x4 col strip.
template <int NOUT, bool RELU, bool HASB2>
__global__ void gemm_kernel(const float* __restrict__ A, const float* __restrict__ B2,
                            const float* __restrict__ W, const float* __restrict__ bias,
                            float* __restrict__ C, int M, int nout_actual, float scale) {
    extern __shared__ float sm[];
    constexpr int COLG = NOUT / 4;    // float4 col groups
    constexpr int ROWS = 256 / COLG;  // rows per pass
    float* Ws = sm;                    // [128][NOUT]
    float* xs = sm + 128 * NOUT;       // [ROWS][128]
    float* bs = xs + ROWS * 128;       // [NOUT]

    for (int i = threadIdx.x; i < 128 * NOUT; i += blockDim.x) {
        int k = i / NOUT, c = i % NOUT;
        Ws[i] = (c < nout_actual) ? W[k * nout_actual + c] : 0.f;
    }
    for (int c = threadIdx.x; c < NOUT; c += blockDim.x)
        bs[c] = (c < nout_actual) ? bias[c] : 0.f;
    __syncthreads();

    const int cg = threadIdx.x % COLG;
    const int r  = threadIdx.x / COLG;
    const float4* Ws4 = (const float4*)Ws;
    const float4 bv = ((const float4*)bs)[cg];

    for (int base = blockIdx.x * ROWS; base < M; base += gridDim.x * ROWS) {
        // stage x rows: scale*A (+ B2)
        for (int i = threadIdx.x; i < ROWS * 32; i += blockDim.x) {
            int rr = i >> 5, c4 = i & 31;
            int row = base + rr;
            float4 v = make_float4(0.f, 0.f, 0.f, 0.f);
            if (row < M) {
                v = ((const float4*)(A + (size_t)row * F))[c4];
                v.x *= scale; v.y *= scale; v.z *= scale; v.w *= scale;
                if (HASB2) {
                    float4 b = ((const float4*)(B2 + (size_t)row * F))[c4];
                    v.x += b.x; v.y += b.y; v.z += b.z; v.w += b.w;
                }
            }
            ((float4*)xs)[i] = v;
        }
        __syncthreads();

        int row = base + r;
        if (row < M) {
            float4 acc = bv;
            const float* xr = xs + r * 128;
#pragma unroll
            for (int k = 0; k < 128; k++) {
                float xv = xr[k];
                float4 w = Ws4[k * COLG + cg];
                acc.x += xv * w.x; acc.y += xv * w.y;
                acc.z += xv * w.z; acc.w += xv * w.w;
            }
            if (RELU) {
                acc.x = fmaxf(acc.x, 0.f); acc.y = fmaxf(acc.y, 0.f);
                acc.z = fmaxf(acc.z, 0.f); acc.w = fmaxf(acc.w, 0.f);
            }
            ((float4*)(C + (size_t)row * NOUT))[cg] = acc;
        }
        __syncthreads();
    }
}

// log_softmax over nc (=47) cols, logits stored with given stride (=64).
__global__ void logsoftmax_kernel(const float* __restrict__ logits, float* __restrict__ out,
                                  int M, int nc, int stride) {
    int warp = (blockIdx.x * blockDim.x + threadIdx.x) >> 5;
    int lane = threadIdx.x & 31;
    if (warp >= M) return;
    const float* rowp = logits + (size_t)warp * stride;
    int c2 = lane + 32;
    float v1 = (lane < nc) ? rowp[lane] : -INFINITY;
    float v2 = (c2 < nc)   ? rowp[c2]   : -INFINITY;
    float mx = fmaxf(v1, v2);
#pragma unroll
    for (int o = 16; o; o >>= 1) mx = fmaxf(mx, __shfl_xor_sync(0xffffffffu, mx, o));
    float s = ((lane < nc) ? expf(v1 - mx) : 0.f) + ((c2 < nc) ? expf(v2 - mx) : 0.f);
#pragma unroll
    for (int o = 16; o; o >>= 1) s += __shfl_xor_sync(0xffffffffu, s, o);
    float lg = logf(s) + mx;
    float* orow = out + (size_t)warp * nc;
    if (lane < nc) orow[lane] = v1 - lg;
    if (c2 < nc)   orow[c2]   = v2 - lg;
}

// ---------------------------------------------------------------------------
extern "C" void kernel_launch(void* const* d_in, const int* in_sizes, int n_in,
                              void* d_out, int out_size) {
    const float* x_in   = (const float*)d_in[0];
    const int*   ei     = (const int*)d_in[1];   // [2,E]: row0 src, row1 tgt
    const int*   ego    = (const int*)d_in[2];   // [2,EGO]: row0 ego_row(write), row1 ego_col(read)
    const float* W_ego0 = (const float*)d_in[3];
    const float* b_ego0 = (const float*)d_in[4];
    const float* W_gin0 = (const float*)d_in[5];
    const float* b_gin0 = (const float*)d_in[6];
    const float* W_ego1 = (const float*)d_in[7];
    const float* b_ego1 = (const float*)d_in[8];
    const float* W_gin1 = (const float*)d_in[9];
    const float* b_gin1 = (const float*)d_in[10];

    int N    = in_sizes[0] / F;
    int E    = in_sizes[1] / 2;
    int EGO  = in_sizes[2] / 2;
    int OUTC = in_sizes[10];
    float invN = 1.0f / (float)N;

    float *pA, *pB, *pC;
    cudaGetSymbolAddress((void**)&pA, g_bufA);
    cudaGetSymbolAddress((void**)&pB, g_bufB);
    cudaGetSymbolAddress((void**)&pC, g_bufC);

    const int n4    = N * F / 4;
    const int ZG    = 592;
    const int GB    = 444;
    const size_t sm128 = (size_t)(128 * 128 + 8 * 128 + 128) * 4;
    const size_t sm64  = (size_t)(128 * 64 + 16 * 128 + 64) * 4;
    cudaFuncSetAttribute(gemm_kernel<128, true, false>,
                         cudaFuncAttributeMaxDynamicSharedMemorySize, (int)sm128);
    cudaFuncSetAttribute(gemm_kernel<128, true, true>,
                         cudaFuncAttributeMaxDynamicSharedMemorySize, (int)sm128);
    cudaFuncSetAttribute(gemm_kernel<64, false, true>,
                         cudaFuncAttributeMaxDynamicSharedMemorySize, (int)sm64);

    int sgEgo = (EGO + 7) / 8;  // 8 warps/block, warp-per-edge
    int sgE   = (E + 7) / 8;

    // ---- layer 0: Ego ----
    zero_kernel<<<ZG, 256>>>(pA, n4);
    scatter_add_kernel<<<sgEgo, 256>>>(x_in, ego, ego + EGO, pA, EGO);
    gemm_kernel<128, true, false><<<GB, 256, sm128>>>(pA, nullptr, W_ego0, b_ego0, pB, N, 128, invN);
    // ---- layer 0: GIN ----
    zero_kernel<<<ZG, 256>>>(pC, n4);
    scatter_add_kernel<<<sgE, 256>>>(pB, ei + E, ei, pC, E);
    gemm_kernel<128, true, true><<<GB, 256, sm128>>>(pB, pC, W_gin0, b_gin0, pA, N, 128, 1.0f);
    // ---- layer 1: Ego ----
    zero_kernel<<<ZG, 256>>>(pB, n4);
    scatter_add_kernel<<<sgEgo, 256>>>(pA, ego, ego + EGO, pB, EGO);
    gemm_kernel<128, true, false><<<GB, 256, sm128>>>(pB, nullptr, W_ego1, b_ego1, pC, N, 128, invN);
    // ---- layer 1: GIN (no end relu) ----
    zero_kernel<<<ZG, 256>>>(pA, n4);
    scatter_add_kernel<<<sgE, 256>>>(pC, ei + E, ei, pA, E);
    gemm_kernel<64, false, true><<<GB, 256, sm64>>>(pC, pA, W_gin1, b_gin1, pB, N, OUTC, 1.0f);
    // ---- log_softmax ----
    int lsg = (N * 32 + 255) / 256;
    logsoftmax_kernel<<<lsg, 256>>>(pB, (float*)d_out, N, OUTC, 64);
}

// round 2
// speedup vs baseline: 1.5072x; 1.5072x over previous
#include <cuda_runtime.h>
#include <math.h>
#include <stdint.h>

#define F 128
#define MAXN 50000

__device__ float g_bufA[MAXN * F];
__device__ float g_bufB[MAXN * F];
__device__ float g_bufC[MAXN * F];

// ---------------------------------------------------------------------------
// scatter: out[widx[e]] += x[ridx[e]], rows of 128 floats. Warp per edge.
__global__ void scatter_add_kernel(const float* __restrict__ x,
                                   const int* __restrict__ widx,
                                   const int* __restrict__ ridx,
                                   float* __restrict__ out, int nedges) {
    int tid   = blockIdx.x * blockDim.x + threadIdx.x;
    int lane  = threadIdx.x & 31;
    int nwarp = (gridDim.x * blockDim.x) >> 5;
    for (int e = tid >> 5; e < nedges; e += nwarp) {
        int w = __ldg(widx + e);
        int r = __ldg(ridx + e);
        float4 v = ((const float4*)(x + (size_t)r * F))[lane];
        float* dst = out + (size_t)w * F + lane * 4;
        asm volatile("red.global.add.v4.f32 [%0], {%1,%2,%3,%4};"
                     :: "l"(dst), "f"(v.x), "f"(v.y), "f"(v.z), "f"(v.w)
                     : "memory");
    }
}

// scatter on 64-wide rows: half-warp per edge (16 lanes x float4 = 64 floats)
__global__ void scatter_add64_kernel(const float* __restrict__ x,
                                     const int* __restrict__ widx,
                                     const int* __restrict__ ridx,
                                     float* __restrict__ out, int nedges) {
    int tid    = blockIdx.x * blockDim.x + threadIdx.x;
    int lane16 = tid & 15;
    int nsub   = (gridDim.x * blockDim.x) >> 4;
    for (int e = tid >> 4; e < nedges; e += nsub) {
        int w = __ldg(widx + e);
        int r = __ldg(ridx + e);
        float4 v = ((const float4*)(x + (size_t)r * 64))[lane16];
        float* dst = out + (size_t)w * 64 + lane16 * 4;
        asm volatile("red.global.add.v4.f32 [%0], {%1,%2,%3,%4};"
                     :: "l"(dst), "f"(v.x), "f"(v.y), "f"(v.z), "f"(v.w)
                     : "memory");
    }
}

// ---------------------------------------------------------------------------
// TF32 tensor-core GEMM: C[M x NCOLS] = act((scale*A (+B2)) @ W[128 x nca] + b)
// Block: 256 thr (8 warps), tile 128 rows x NCOLS cols. Warp: 32 rows x NCOLS/2.
__device__ __forceinline__ uint32_t f2tf32(float f) {
    uint32_t u;
    asm("cvt.rna.tf32.f32 %0, %1;" : "=r"(u) : "f"(f));
    return u;
}
__device__ __forceinline__ void mma_tf32(float& c0, float& c1, float& c2, float& c3,
                                         uint32_t a0, uint32_t a1, uint32_t a2, uint32_t a3,
                                         uint32_t b0, uint32_t b1) {
    asm volatile(
        "mma.sync.aligned.m16n8k8.row.col.f32.tf32.tf32.f32 "
        "{%0,%1,%2,%3}, {%4,%5,%6,%7}, {%8,%9}, {%0,%1,%2,%3};"
        : "+f"(c0), "+f"(c1), "+f"(c2), "+f"(c3)
        : "r"(a0), "r"(a1), "r"(a2), "r"(a3), "r"(b0), "r"(b1));
}

template <int NCOLS, bool RELU, bool HASB2, bool BIAS>
__global__ void __launch_bounds__(256, 1)
gemm_tc_kernel(const float* __restrict__ A, const float* __restrict__ B2,
               const float* __restrict__ W, const float* __restrict__ bias,
               float* __restrict__ C, int M, int nca, float scale) {
    constexpr int PW = NCOLS + 8;  // W row pad -> 8t+g conflict-free B frags
    constexpr int PA = 132;        // A row pad -> 4g+t conflict-free A frags
    constexpr int HC = NCOLS / 2;  // warp col span
    constexpr int NT = HC / 8;     // n-tiles per warp

    extern __shared__ float sm[];
    uint32_t* Ws = (uint32_t*)sm;              // [128][PW] tf32
    uint32_t* As = (uint32_t*)(sm + 128 * PW); // [128][PA] tf32
    __shared__ float bs[NCOLS];

    const int tid  = threadIdx.x;
    const int lane = tid & 31;
    const int warp = tid >> 5;
    const int wr   = warp >> 1;  // 0..3
    const int wc   = warp & 1;   // 0..1
    const int g    = lane >> 2;  // 0..7
    const int t    = lane & 3;   // 0..3

    // stage W (tf32, zero-padded cols)
    for (int i = tid; i < 128 * NCOLS; i += 256) {
        int k = i / NCOLS, c = i % NCOLS;
        float w = (c < nca) ? W[k * nca + c] : 0.f;
        Ws[k * PW + c] = f2tf32(w);
    }
    if (BIAS)
        for (int c = tid; c < NCOLS; c += 256) bs[c] = (c < nca) ? bias[c] : 0.f;

    const int base = blockIdx.x * 128;
    // stage A chunk (scale, optional add, tf32 convert)
    for (int i = tid; i < 128 * 32; i += 256) {
        int rr = i >> 5, c4 = i & 31;
        int row = base + rr;
        uint4 u = make_uint4(0u, 0u, 0u, 0u);
        if (row < M) {
            float4 v = ((const float4*)(A + (size_t)row * 128))[c4];
            v.x *= scale; v.y *= scale; v.z *= scale; v.w *= scale;
            if (HASB2) {
                float4 b = ((const float4*)(B2 + (size_t)row * 128))[c4];
                v.x += b.x; v.y += b.y; v.z += b.z; v.w += b.w;
            }
            u.x = f2tf32(v.x); u.y = f2tf32(v.y); u.z = f2tf32(v.z); u.w = f2tf32(v.w);
        }
        ((uint4*)(As + rr * PA))[c4] = u;
    }
    __syncthreads();

    float acc[2][NT][4];
#pragma unroll
    for (int mi = 0; mi < 2; mi++)
#pragma unroll
        for (int nt = 0; nt < NT; nt++)
#pragma unroll
            for (int j = 0; j < 4; j++) acc[mi][nt][j] = 0.f;

#pragma unroll
    for (int ks = 0; ks < 16; ks++) {
        const int k0 = ks * 8;
        uint32_t a[2][4];
#pragma unroll
        for (int mi = 0; mi < 2; mi++) {
            int r = wr * 32 + mi * 16 + g;
            a[mi][0] = As[r * PA + k0 + t];
            a[mi][1] = As[(r + 8) * PA + k0 + t];
            a[mi][2] = As[r * PA + k0 + t + 4];
            a[mi][3] = As[(r + 8) * PA + k0 + t + 4];
        }
#pragma unroll
        for (int nt = 0; nt < NT; nt++) {
            int n = wc * HC + nt * 8 + g;
            uint32_t b0 = Ws[(k0 + t) * PW + n];
            uint32_t b1 = Ws[(k0 + t + 4) * PW + n];
#pragma unroll
            for (int mi = 0; mi < 2; mi++)
                mma_tf32(acc[mi][nt][0], acc[mi][nt][1], acc[mi][nt][2], acc[mi][nt][3],
                         a[mi][0], a[mi][1], a[mi][2], a[mi][3], b0, b1);
        }
    }

    // epilogue: bias, relu, store (stride NCOLS)
#pragma unroll
    for (int mi = 0; mi < 2; mi++) {
        int r0 = base + wr * 32 + mi * 16 + g;
        int r1 = r0 + 8;
#pragma unroll
        for (int nt = 0; nt < NT; nt++) {
            int col = wc * HC + nt * 8 + t * 2;
            float bx = BIAS ? bs[col] : 0.f;
            float by = BIAS ? bs[col + 1] : 0.f;
            float2 v0 = make_float2(acc[mi][nt][0] + bx, acc[mi][nt][1] + by);
            float2 v1 = make_float2(acc[mi][nt][2] + bx, acc[mi][nt][3] + by);
            if (RELU) {
                v0.x = fmaxf(v0.x, 0.f); v0.y = fmaxf(v0.y, 0.f);
                v1.x = fmaxf(v1.x, 0.f); v1.y = fmaxf(v1.y, 0.f);
            }
            if (r0 < M) *(float2*)(C + (size_t)r0 * NCOLS + col) = v0;
            if (r1 < M) *(float2*)(C + (size_t)r1 * NCOLS + col) = v1;
        }
    }
}

// ---------------------------------------------------------------------------
// out = log_softmax(y + aggr + bias) over nc=47 cols; y/aggr stride 64.
__global__ void final_logsoftmax_kernel(const float* __restrict__ y,
                                        const float* __restrict__ aggr,
                                        const float* __restrict__ bias,
                                        float* __restrict__ out, int M, int nc) {
    int warp = (blockIdx.x * blockDim.x + threadIdx.x) >> 5;
    int lane = threadIdx.x & 31;
    if (warp >= M) return;
    const float* yp = y + (size_t)warp * 64;
    const float* ap = aggr + (size_t)warp * 64;
    int c2 = lane + 32;
    float v1 = (lane < nc) ? yp[lane] + ap[lane] + __ldg(bias + lane) : -INFINITY;
    float v2 = (c2 < nc)   ? yp[c2] + ap[c2] + __ldg(bias + c2)       : -INFINITY;
    float mx = fmaxf(v1, v2);
#pragma unroll
    for (int o = 16; o; o >>= 1) mx = fmaxf(mx, __shfl_xor_sync(0xffffffffu, mx, o));
    float s = ((lane < nc) ? expf(v1 - mx) : 0.f) + ((c2 < nc) ? expf(v2 - mx) : 0.f);
#pragma unroll
    for (int o = 16; o; o >>= 1) s += __shfl_xor_sync(0xffffffffu, s, o);
    float lg = logf(s) + mx;
    float* orow = out + (size_t)warp * nc;
    if (lane < nc) orow[lane] = v1 - lg;
    if (c2 < nc)   orow[c2]   = v2 - lg;
}

// ---------------------------------------------------------------------------
extern "C" void kernel_launch(void* const* d_in, const int* in_sizes, int n_in,
                              void* d_out, int out_size) {
    const float* x_in   = (const float*)d_in[0];
    const int*   ei     = (const int*)d_in[1];
    const int*   ego    = (const int*)d_in[2];
    const float* W_ego0 = (const float*)d_in[3];
    const float* b_ego0 = (const float*)d_in[4];
    const float* W_gin0 = (const float*)d_in[5];
    const float* b_gin0 = (const float*)d_in[6];
    const float* W_ego1 = (const float*)d_in[7];
    const float* b_ego1 = (const float*)d_in[8];
    const float* W_gin1 = (const float*)d_in[9];
    const float* b_gin1 = (const float*)d_in[10];

    int N    = in_sizes[0] / F;
    int E    = in_sizes[1] / 2;
    int EGO  = in_sizes[2] / 2;
    int OUTC = in_sizes[10];
    float invN = 1.0f / (float)N;

    float *pA, *pB, *pC;
    cudaGetSymbolAddress((void**)&pA, g_bufA);
    cudaGetSymbolAddress((void**)&pB, g_bufB);
    cudaGetSymbolAddress((void**)&pC, g_bufC);

    const size_t sm128 = (size_t)(128 * (128 + 8) + 128 * 132) * 4;
    const size_t sm64  = (size_t)(128 * (64 + 8) + 128 * 132) * 4;
    cudaFuncSetAttribute(gemm_tc_kernel<128, true, false, true>,
                         cudaFuncAttributeMaxDynamicSharedMemorySize, (int)sm128);
    cudaFuncSetAttribute(gemm_tc_kernel<128, true, true, true>,
                         cudaFuncAttributeMaxDynamicSharedMemorySize, (int)sm128);
    cudaFuncSetAttribute(gemm_tc_kernel<64, false, false, false>,
                         cudaFuncAttributeMaxDynamicSharedMemorySize, (int)sm64);

    int GR    = (N + 127) / 128;      // gemm blocks
    int sgEgo = (EGO + 7) / 8;        // warp-per-edge
    int sgE   = (E + 7) / 8;
    int sgE64 = (E + 15) / 16;        // half-warp-per-edge
    size_t bytes128 = (size_t)N * 128 * sizeof(float);
    size_t bytes64  = (size_t)N * 64 * sizeof(float);

    // layer 0: Ego
    cudaMemsetAsync(pA, 0, bytes128, 0);
    scatter_add_kernel<<<sgEgo, 256>>>(x_in, ego, ego + EGO, pA, EGO);
    gemm_tc_kernel<128, true, false, true><<<GR, 256, sm128>>>(
        pA, nullptr, W_ego0, b_ego0, pB, N, 128, invN);
    // layer 0: GIN
    cudaMemsetAsync(pC, 0, bytes128, 0);
    scatter_add_kernel<<<sgE, 256>>>(pB, ei + E, ei, pC, E);
    gemm_tc_kernel<128, true, true, true><<<GR, 256, sm128>>>(
        pB, pC, W_gin0, b_gin0, pA, N, 128, 1.0f);
    // layer 1: Ego
    cudaMemsetAsync(pB, 0, bytes128, 0);
    scatter_add_kernel<<<sgEgo, 256>>>(pA, ego, ego + EGO, pB, EGO);
    gemm_tc_kernel<128, true, false, true><<<GR, 256, sm128>>>(
        pB, nullptr, W_ego1, b_ego1, pC, N, 128, invN);
    // layer 1: GIN via linearity: y = x@W ; out = y + segsum(y) + b
    gemm_tc_kernel<64, false, false, false><<<GR, 256, sm64>>>(
        pC, nullptr, W_gin1, nullptr, pA, N, OUTC, 1.0f);
    cudaMemsetAsync(pB, 0, bytes64, 0);
    scatter_add64_kernel<<<sgE64, 256>>>(pA, ei + E, ei, pB, E);
    // fused add + bias + log_softmax
    int lsg = (N * 32 + 255) / 256;
    final_logsoftmax_kernel<<<lsg, 256>>>(pA, pB, b_gin1, (float*)d_out, N, OUTC);
}

// round 3
// speedup vs baseline: 1.6594x; 1.1010x over previous
#include <cuda_runtime.h>
#include <math.h>
#include <stdint.h>

#define F 128
#define MAXN 50000

__device__ float g_bufA[MAXN * F];
__device__ float g_bufB[MAXN * F];
__device__ float g_bufC[MAXN * F];

// ---------------------------------------------------------------------------
// scatter: out[widx[e]] += x[ridx[e]], rows of 128 floats. Warp per edge.
__global__ void scatter_add_kernel(const float* __restrict__ x,
                                   const int* __restrict__ widx,
                                   const int* __restrict__ ridx,
                                   float* __restrict__ out, int nedges) {
    int tid   = blockIdx.x * blockDim.x + threadIdx.x;
    int lane  = threadIdx.x & 31;
    int nwarp = (gridDim.x * blockDim.x) >> 5;
    for (int e = tid >> 5; e < nedges; e += nwarp) {
        int w = __ldg(widx + e);
        int r = __ldg(ridx + e);
        float4 v = ((const float4*)(x + (size_t)r * F))[lane];
        float* dst = out + (size_t)w * F + lane * 4;
        asm volatile("red.global.add.v4.f32 [%0], {%1,%2,%3,%4};"
                     :: "l"(dst), "f"(v.x), "f"(v.y), "f"(v.z), "f"(v.w)
                     : "memory");
    }
}

// scatter on 64-wide rows: half-warp per edge
__global__ void scatter_add64_kernel(const float* __restrict__ x,
                                     const int* __restrict__ widx,
                                     const int* __restrict__ ridx,
                                     float* __restrict__ out, int nedges) {
    int tid    = blockIdx.x * blockDim.x + threadIdx.x;
    int lane16 = tid & 15;
    int nsub   = (gridDim.x * blockDim.x) >> 4;
    for (int e = tid >> 4; e < nedges; e += nsub) {
        int w = __ldg(widx + e);
        int r = __ldg(ridx + e);
        float4 v = ((const float4*)(x + (size_t)r * 64))[lane16];
        float* dst = out + (size_t)w * 64 + lane16 * 4;
        asm volatile("red.global.add.v4.f32 [%0], {%1,%2,%3,%4};"
                     :: "l"(dst), "f"(v.x), "f"(v.y), "f"(v.z), "f"(v.w)
                     : "memory");
    }
}

// ---------------------------------------------------------------------------
// TF32 tensor-core GEMM, 64x64 tile per CTA (grid.y = col tile of 64).
// C[M x ncstride] = act((scale*A (+B2)) @ W[128 x nca] + b)
__device__ __forceinline__ uint32_t f2tf32(float f) {
    uint32_t u;
    asm("cvt.rna.tf32.f32 %0, %1;" : "=r"(u) : "f"(f));
    return u;
}
__device__ __forceinline__ void mma_tf32(float& c0, float& c1, float& c2, float& c3,
                                         uint32_t a0, uint32_t a1, uint32_t a2, uint32_t a3,
                                         uint32_t b0, uint32_t b1) {
    asm volatile(
        "mma.sync.aligned.m16n8k8.row.col.f32.tf32.tf32.f32 "
        "{%0,%1,%2,%3}, {%4,%5,%6,%7}, {%8,%9}, {%0,%1,%2,%3};"
        : "+f"(c0), "+f"(c1), "+f"(c2), "+f"(c3)
        : "r"(a0), "r"(a1), "r"(a2), "r"(a3), "r"(b0), "r"(b1));
}

template <bool RELU, bool HASB2, bool BIAS, bool VECW>
__global__ void __launch_bounds__(256, 3)
gemm_tc_kernel(const float* __restrict__ A, const float* __restrict__ B2,
               const float* __restrict__ W, const float* __restrict__ bias,
               float* __restrict__ C, int M, int nca, int ncstride, float scale) {
    constexpr int PW = 72;   // 64 cols + 8 pad (conflict-free B frags)
    constexpr int PA = 132;  // 128 + 4 pad (conflict-free A frags)

    extern __shared__ float sm[];
    uint32_t* Ws = (uint32_t*)sm;              // [128][72] tf32
    uint32_t* As = (uint32_t*)(sm + 128 * PW); // [64][132] tf32
    __shared__ float bs[64];

    const int tid  = threadIdx.x;
    const int lane = tid & 31;
    const int warp = tid >> 5;
    const int wr   = warp >> 1;  // 0..3 (16-row group)
    const int wc   = warp & 1;   // 0..1 (32-col group)
    const int g    = lane >> 2;  // 0..7
    const int t    = lane & 3;   // 0..3
    const int cb   = blockIdx.y * 64;  // col-tile base

    // stage W (tf32)
    if (VECW) {
        // nca multiple of 4, all 64 cols valid: coalesced float4
#pragma unroll
        for (int i = tid; i < 128 * 16; i += 256) {
            int k = i >> 4, c4 = i & 15;
            float4 v = __ldg((const float4*)(W + (size_t)k * nca + cb) + c4);
            uint4 u;
            u.x = f2tf32(v.x); u.y = f2tf32(v.y); u.z = f2tf32(v.z); u.w = f2tf32(v.w);
            *(uint4*)(Ws + k * PW + c4 * 4) = u;
        }
    } else {
#pragma unroll
        for (int i = tid; i < 128 * 64; i += 256) {
            int k = i >> 6, c = i & 63;
            int gc = cb + c;
            float w = (gc < nca) ? __ldg(W + (size_t)k * nca + gc) : 0.f;
            Ws[k * PW + c] = f2tf32(w);
        }
    }
    if (BIAS && tid < 64) bs[tid] = (cb + tid < nca) ? bias[cb + tid] : 0.f;

    const int base = blockIdx.x * 64;
    // stage A tile (scale, optional add, tf32 convert)
#pragma unroll
    for (int i = tid; i < 64 * 32; i += 256) {
        int rr = i >> 5, c4 = i & 31;
        int row = base + rr;
        uint4 u = make_uint4(0u, 0u, 0u, 0u);
        if (row < M) {
            float4 v = ((const float4*)(A + (size_t)row * 128))[c4];
            v.x *= scale; v.y *= scale; v.z *= scale; v.w *= scale;
            if (HASB2) {
                float4 b = ((const float4*)(B2 + (size_t)row * 128))[c4];
                v.x += b.x; v.y += b.y; v.z += b.z; v.w += b.w;
            }
            u.x = f2tf32(v.x); u.y = f2tf32(v.y); u.z = f2tf32(v.z); u.w = f2tf32(v.w);
        }
        ((uint4*)(As + rr * PA))[c4] = u;
    }
    __syncthreads();

    float acc[4][4];
#pragma unroll
    for (int nt = 0; nt < 4; nt++)
#pragma unroll
        for (int j = 0; j < 4; j++) acc[nt][j] = 0.f;

    const int r0 = wr * 16 + g;
#pragma unroll
    for (int ks = 0; ks < 16; ks++) {
        const int k0 = ks * 8;
        uint32_t a0 = As[r0 * PA + k0 + t];
        uint32_t a1 = As[(r0 + 8) * PA + k0 + t];
        uint32_t a2 = As[r0 * PA + k0 + t + 4];
        uint32_t a3 = As[(r0 + 8) * PA + k0 + t + 4];
#pragma unroll
        for (int nt = 0; nt < 4; nt++) {
            int n = wc * 32 + nt * 8 + g;
            uint32_t b0 = Ws[(k0 + t) * PW + n];
            uint32_t b1 = Ws[(k0 + t + 4) * PW + n];
            mma_tf32(acc[nt][0], acc[nt][1], acc[nt][2], acc[nt][3],
                     a0, a1, a2, a3, b0, b1);
        }
    }

    // epilogue
    int gr0 = base + wr * 16 + g;
    int gr1 = gr0 + 8;
#pragma unroll
    for (int nt = 0; nt < 4; nt++) {
        int col = wc * 32 + nt * 8 + t * 2;
        float bx = BIAS ? bs[col] : 0.f;
        float by = BIAS ? bs[col + 1] : 0.f;
        float2 v0 = make_float2(acc[nt][0] + bx, acc[nt][1] + by);
        float2 v1 = make_float2(acc[nt][2] + bx, acc[nt][3] + by);
        if (RELU) {
            v0.x = fmaxf(v0.x, 0.f); v0.y = fmaxf(v0.y, 0.f);
            v1.x = fmaxf(v1.x, 0.f); v1.y = fmaxf(v1.y, 0.f);
        }
        int gcol = cb + col;
        if (gr0 < M) *(float2*)(C + (size_t)gr0 * ncstride + gcol) = v0;
        if (gr1 < M) *(float2*)(C + (size_t)gr1 * ncstride + gcol) = v1;
    }
}

// ---------------------------------------------------------------------------
// out = log_softmax(y + aggr + bias) over nc=47 cols; y/aggr stride 64.
__global__ void final_logsoftmax_kernel(const float* __restrict__ y,
                                        const float* __restrict__ aggr,
                                        const float* __restrict__ bias,
                                        float* __restrict__ out, int M, int nc) {
    int warp = (blockIdx.x * blockDim.x + threadIdx.x) >> 5;
    int lane = threadIdx.x & 31;
    if (warp >= M) return;
    const float* yp = y + (size_t)warp * 64;
    const float* ap = aggr + (size_t)warp * 64;
    int c2 = lane + 32;
    float v1 = (lane < nc) ? yp[lane] + ap[lane] + __ldg(bias + lane) : -INFINITY;
    float v2 = (c2 < nc)   ? yp[c2] + ap[c2] + __ldg(bias + c2)       : -INFINITY;
    float mx = fmaxf(v1, v2);
#pragma unroll
    for (int o = 16; o; o >>= 1) mx = fmaxf(mx, __shfl_xor_sync(0xffffffffu, mx, o));
    float s = ((lane < nc) ? expf(v1 - mx) : 0.f) + ((c2 < nc) ? expf(v2 - mx) : 0.f);
#pragma unroll
    for (int o = 16; o; o >>= 1) s += __shfl_xor_sync(0xffffffffu, s, o);
    float lg = logf(s) + mx;
    float* orow = out + (size_t)warp * nc;
    if (lane < nc) orow[lane] = v1 - lg;
    if (c2 < nc)   orow[c2]   = v2 - lg;
}

// ---------------------------------------------------------------------------
extern "C" void kernel_launch(void* const* d_in, const int* in_sizes, int n_in,
                              void* d_out, int out_size) {
    const float* x_in   = (const float*)d_in[0];
    const int*   ei     = (const int*)d_in[1];
    const int*   ego    = (const int*)d_in[2];
    const float* W_ego0 = (const float*)d_in[3];
    const float* b_ego0 = (const float*)d_in[4];
    const float* W_gin0 = (const float*)d_in[5];
    const float* b_gin0 = (const float*)d_in[6];
    const float* W_ego1 = (const float*)d_in[7];
    const float* b_ego1 = (const float*)d_in[8];
    const float* W_gin1 = (const float*)d_in[9];
    const float* b_gin1 = (const float*)d_in[10];

    int N    = in_sizes[0] / F;
    int E    = in_sizes[1] / 2;
    int EGO  = in_sizes[2] / 2;
    int OUTC = in_sizes[10];
    float invN = 1.0f / (float)N;

    float *pA, *pB, *pC;
    cudaGetSymbolAddress((void**)&pA, g_bufA);
    cudaGetSymbolAddress((void**)&pB, g_bufB);
    cudaGetSymbolAddress((void**)&pC, g_bufC);

    const size_t smg = (size_t)(128 * 72 + 64 * 132) * 4;  // 70656
    cudaFuncSetAttribute(gemm_tc_kernel<true, false, true, true>,
                         cudaFuncAttributeMaxDynamicSharedMemorySize, (int)smg);
    cudaFuncSetAttribute(gemm_tc_kernel<true, true, true, true>,
                         cudaFuncAttributeMaxDynamicSharedMemorySize, (int)smg);
    cudaFuncSetAttribute(gemm_tc_kernel<false, false, false, false>,
                         cudaFuncAttributeMaxDynamicSharedMemorySize, (int)smg);

    dim3 g128((N + 63) / 64, 2);
    dim3 g64((N + 63) / 64, 1);
    int sgEgo = (EGO + 7) / 8;
    int sgE   = (E + 7) / 8;
    int sgE64 = (E + 15) / 16;
    size_t bytes128 = (size_t)N * 128 * sizeof(float);
    size_t bytes64  = (size_t)N * 64 * sizeof(float);

    // layer 0: Ego
    cudaMemsetAsync(pA, 0, bytes128, 0);
    scatter_add_kernel<<<sgEgo, 256>>>(x_in, ego, ego + EGO, pA, EGO);
    gemm_tc_kernel<true, false, true, true><<<g128, 256, smg>>>(
        pA, nullptr, W_ego0, b_ego0, pB, N, 128, 128, invN);
    // layer 0: GIN
    cudaMemsetAsync(pC, 0, bytes128, 0);
    scatter_add_kernel<<<sgE, 256>>>(pB, ei + E, ei, pC, E);
    gemm_tc_kernel<true, true, true, true><<<g128, 256, smg>>>(
        pB, pC, W_gin0, b_gin0, pA, N, 128, 128, 1.0f);
    // layer 1: Ego
    cudaMemsetAsync(pB, 0, bytes128, 0);
    scatter_add_kernel<<<sgEgo, 256>>>(pA, ego, ego + EGO, pB, EGO);
    gemm_tc_kernel<true, false, true, true><<<g128, 256, smg>>>(
        pB, nullptr, W_ego1, b_ego1, pC, N, 128, 128, invN);
    // layer 1: GIN via linearity: y = x@W ; out = y + segsum(y) + b
    gemm_tc_kernel<false, false, false, false><<<g64, 256, smg>>>(
        pC, nullptr, W_gin1, nullptr, pA, N, OUTC, 64, 1.0f);
    cudaMemsetAsync(pB, 0, bytes64, 0);
    scatter_add64_kernel<<<sgE64, 256>>>(pA, ei + E, ei, pB, E);
    // fused add + bias + log_softmax
    int lsg = (N * 32 + 255) / 256;
    final_logsoftmax_kernel<<<lsg, 256>>>(pA, pB, b_gin1, (float*)d_out, N, OUTC);
}